// round 1
// baseline (speedup 1.0000x reference)
#include <cuda_runtime.h>

#define DEV_INLINE __device__ __forceinline__

constexpr int B_ = 8;
constexpr int C_ = 256;
constexpr int CI = 32;
constexpr int N_ = 4096;
constexpr float L2E = 1.4426950408889634f;

// Scratch (device globals: no allocation in kernel_launch).
__device__ float g_y1[B_ * CI * N_];   // 4 MB each, L2-resident
__device__ float g_y2[B_ * CI * N_];
__device__ float g_y3[B_ * CI * N_];
__device__ float g_alpha[B_ * N_];     // alpha[n] = M[n]*log2e + log2(Z[n])
__device__ float g_wT[3][C_][CI];      // w1/w2/w3 transposed to [k][co]

DEV_INLINE float fexp2(float v) { float y; asm("ex2.approx.ftz.f32 %0, %1;" : "=f"(y) : "f"(v)); return y; }
DEV_INLINE float flog2(float v) { float y; asm("lg2.approx.ftz.f32 %0, %1;" : "=f"(y) : "f"(v)); return y; }

// ---------------------------------------------------------------------------
// K0: transpose the three 32x256 conv weights into [k][co] for coalesced use.
// ---------------------------------------------------------------------------
__global__ void k0_transpose(const float* __restrict__ w1,
                             const float* __restrict__ w2,
                             const float* __restrict__ w3) {
    const float* w = blockIdx.x == 0 ? w1 : blockIdx.x == 1 ? w2 : w3;
    float* dst = &g_wT[blockIdx.x][0][0];
    for (int i = threadIdx.x; i < C_ * CI; i += blockDim.x) {
        int co = i / C_;
        int k  = i - co * C_;
        dst[k * CI + co] = w[i];
    }
}

// ---------------------------------------------------------------------------
// K1: y{1,2,3}[b][co][m] = SiLU( (w @ x)*s + bias ).
// One thread per spatial position m; 32 fp32 accumulators; w tile in smem.
// grid = (B*N/128, 3), block = 128
// ---------------------------------------------------------------------------
__global__ void __launch_bounds__(128) k1_conv(
    const float* __restrict__ x,
    const float* __restrict__ s1, const float* __restrict__ b1,
    const float* __restrict__ s2, const float* __restrict__ b2,
    const float* __restrict__ s3, const float* __restrict__ b3) {
    __shared__ float wTs[C_ * CI];  // 32 KB
    int which = blockIdx.y;
    const float* sc = which == 0 ? s1 : which == 1 ? s2 : s3;
    const float* bi = which == 0 ? b1 : which == 1 ? b2 : b3;
    float* yout = which == 0 ? g_y1 : which == 1 ? g_y2 : g_y3;
    const float* wT = &g_wT[which][0][0];
    int tid = threadIdx.x;
    for (int i = tid * 4; i < C_ * CI; i += 128 * 4)
        *(float4*)&wTs[i] = *(const float4*)&wT[i];
    __syncthreads();

    int g = blockIdx.x * 128 + tid;
    int b = g / N_;
    int m = g - b * N_;
    const float* xp = x + b * C_ * N_ + m;

    float acc[CI];
#pragma unroll
    for (int j = 0; j < CI; j++) acc[j] = 0.f;

#pragma unroll 4
    for (int k = 0; k < C_; k++) {
        float xv = __ldg(xp + k * N_);
        const float* wr = &wTs[k * CI];
#pragma unroll
        for (int j = 0; j < CI; j += 4) {
            float4 wv = *(const float4*)&wr[j];
            acc[j + 0] = fmaf(xv, wv.x, acc[j + 0]);
            acc[j + 1] = fmaf(xv, wv.y, acc[j + 1]);
            acc[j + 2] = fmaf(xv, wv.z, acc[j + 2]);
            acc[j + 3] = fmaf(xv, wv.w, acc[j + 3]);
        }
    }

    float* yp = yout + b * CI * N_ + m;
#pragma unroll
    for (int j = 0; j < CI; j++) {
        float y = fmaf(acc[j], __ldg(sc + j), __ldg(bi + j));
        float sg = 1.f / (1.f + fexp2(-y * L2E));
        yp[j * N_] = y * sg;
    }
}

// ---------------------------------------------------------------------------
// K2: per-row online softmax stats of c[n,m] = sum_k y2[k,n]*y1[k,m].
// Block: 256 thr = 16x16; block owns 64 rows n, streams all m in 64-wide
// tiles. Each thread computes a 4x4 c micro-tile (float4 LDS, 16 FFMA/k).
// grid = (N/64, B)
// ---------------------------------------------------------------------------
__global__ void __launch_bounds__(256) k2_stats() {
    __shared__ float As[CI * 64];  // y2 tile [k][n]
    __shared__ float Bs[CI * 64];  // y1 tile [k][m]
    int b = blockIdx.y;
    int n0 = blockIdx.x * 64;
    int tid = threadIdx.x;
    int tx = tid & 15, ty = tid >> 4;
    const float* y2b = g_y2 + b * CI * N_;
    const float* y1b = g_y1 + b * CI * N_;

#pragma unroll
    for (int i = tid; i < CI * 16; i += 256) {
        int k = i >> 4, c4 = (i & 15) << 2;
        *(float4*)&As[k * 64 + c4] = *(const float4*)&y2b[k * N_ + n0 + c4];
    }

    float runM[4], runL[4];
#pragma unroll
    for (int i = 0; i < 4; i++) { runM[i] = -3.0e38f; runL[i] = 0.f; }

    for (int m0 = 0; m0 < N_; m0 += 64) {
        __syncthreads();
#pragma unroll
        for (int i = tid; i < CI * 16; i += 256) {
            int k = i >> 4, c4 = (i & 15) << 2;
            *(float4*)&Bs[k * 64 + c4] = *(const float4*)&y1b[k * N_ + m0 + c4];
        }
        __syncthreads();

        float c[4][4];
#pragma unroll
        for (int i = 0; i < 4; i++)
#pragma unroll
            for (int j = 0; j < 4; j++) c[i][j] = 0.f;

#pragma unroll
        for (int k = 0; k < CI; k++) {
            float4 a  = *(const float4*)&As[k * 64 + ty * 4];
            float4 bb = *(const float4*)&Bs[k * 64 + tx * 4];
            float av[4] = {a.x, a.y, a.z, a.w};
            float bv[4] = {bb.x, bb.y, bb.z, bb.w};
#pragma unroll
            for (int i = 0; i < 4; i++)
#pragma unroll
                for (int j = 0; j < 4; j++)
                    c[i][j] = fmaf(av[i], bv[j], c[i][j]);
        }

        // online softmax update (per row, reduced across the 16 tx lanes)
#pragma unroll
        for (int i = 0; i < 4; i++) {
            float mx = fmaxf(fmaxf(c[i][0], c[i][1]), fmaxf(c[i][2], c[i][3]));
#pragma unroll
            for (int o = 1; o < 16; o <<= 1)
                mx = fmaxf(mx, __shfl_xor_sync(0xffffffffu, mx, o, 16));
            float newM = fmaxf(runM[i], mx);
            float s = fexp2((c[i][0] - newM) * L2E) + fexp2((c[i][1] - newM) * L2E)
                    + fexp2((c[i][2] - newM) * L2E) + fexp2((c[i][3] - newM) * L2E);
#pragma unroll
            for (int o = 1; o < 16; o <<= 1)
                s += __shfl_xor_sync(0xffffffffu, s, o, 16);
            runL[i] = runL[i] * fexp2((runM[i] - newM) * L2E) + s;
            runM[i] = newM;
        }
    }

    if (tx == 0) {
#pragma unroll
        for (int i = 0; i < 4; i++)
            g_alpha[b * N_ + n0 + ty * 4 + i] = fmaf(runM[i], L2E, flog2(runL[i]));
    }
}

// ---------------------------------------------------------------------------
// K3: y_last[:,m-tile] = sum_n y3[:,n] * exp2(c[n,m]*L2E - alpha[n]),
// then fused final conv (w4, s4, b4) + SiLU + residual -> out.
// Block owns a 64-wide m tile; loops n tiles: GEMM1 (c, regs) -> P (smem)
// -> GEMM2 (acc += y3 @ P). grid = (N/64, B), block 256.
// ---------------------------------------------------------------------------
__global__ void __launch_bounds__(256) k3_attn(
    const float* __restrict__ w4, const float* __restrict__ s4,
    const float* __restrict__ b4, const float* __restrict__ x,
    float* __restrict__ out) {
    __shared__ float pool[11008];  // 43 KB
    float* As  = pool;             // [32][64]  y2 n-tile
    float* Vs  = pool + 2048;      // [32][64]  y3 n-tile
    float* B1s = pool + 4096;      // [32][64]  y1 m-tile (loaded once)
    float* Ps  = pool + 6144;      // [64][68]  P tile (padded)

    int b = blockIdx.y;
    int m0 = blockIdx.x * 64;
    int tid = threadIdx.x;
    int tx = tid & 15, ty = tid >> 4;
    const float* y1b = g_y1 + b * CI * N_;
    const float* y2b = g_y2 + b * CI * N_;
    const float* y3b = g_y3 + b * CI * N_;

#pragma unroll
    for (int i = tid; i < CI * 16; i += 256) {
        int k = i >> 4, c4 = (i & 15) << 2;
        *(float4*)&B1s[k * 64 + c4] = *(const float4*)&y1b[k * N_ + m0 + c4];
    }

    float acc[2][4];
#pragma unroll
    for (int i = 0; i < 2; i++)
#pragma unroll
        for (int j = 0; j < 4; j++) acc[i][j] = 0.f;

    for (int n0 = 0; n0 < N_; n0 += 64) {
        __syncthreads();  // previous GEMM2 done (Ps/Vs reusable)
#pragma unroll
        for (int i = tid; i < CI * 16; i += 256) {
            int k = i >> 4, c4 = (i & 15) << 2;
            *(float4*)&As[k * 64 + c4] = *(const float4*)&y2b[k * N_ + n0 + c4];
            *(float4*)&Vs[k * 64 + c4] = *(const float4*)&y3b[k * N_ + n0 + c4];
        }
        __syncthreads();

        // GEMM1: c[i][j], rows n0+ty*4+i, cols m0+tx*4+j
        float c[4][4];
#pragma unroll
        for (int i = 0; i < 4; i++)
#pragma unroll
            for (int j = 0; j < 4; j++) c[i][j] = 0.f;
#pragma unroll
        for (int k = 0; k < CI; k++) {
            float4 a  = *(const float4*)&As[k * 64 + ty * 4];
            float4 bb = *(const float4*)&B1s[k * 64 + tx * 4];
            float av[4] = {a.x, a.y, a.z, a.w};
            float bv[4] = {bb.x, bb.y, bb.z, bb.w};
#pragma unroll
            for (int i = 0; i < 4; i++)
#pragma unroll
                for (int j = 0; j < 4; j++)
                    c[i][j] = fmaf(av[i], bv[j], c[i][j]);
        }

        // P = exp2(c*L2E - alpha[n]); write to smem
        float4 al = *(const float4*)&g_alpha[b * N_ + n0 + ty * 4];
        float alv[4] = {al.x, al.y, al.z, al.w};
#pragma unroll
        for (int i = 0; i < 4; i++) {
            float4 p;
            p.x = fexp2(fmaf(c[i][0], L2E, -alv[i]));
            p.y = fexp2(fmaf(c[i][1], L2E, -alv[i]));
            p.z = fexp2(fmaf(c[i][2], L2E, -alv[i]));
            p.w = fexp2(fmaf(c[i][3], L2E, -alv[i]));
            *(float4*)&Ps[(ty * 4 + i) * 68 + tx * 4] = p;
        }
        __syncthreads();

        // GEMM2: acc[ci=ty*2+i][m=tx*4+j] += sum_nn Vs[ci][nn]*Ps[nn][m]
#pragma unroll 8
        for (int nn = 0; nn < 64; ++nn) {
            float v0 = Vs[(ty * 2 + 0) * 64 + nn];
            float v1 = Vs[(ty * 2 + 1) * 64 + nn];
            float4 p4 = *(const float4*)&Ps[nn * 68 + tx * 4];
            acc[0][0] = fmaf(v0, p4.x, acc[0][0]);
            acc[0][1] = fmaf(v0, p4.y, acc[0][1]);
            acc[0][2] = fmaf(v0, p4.z, acc[0][2]);
            acc[0][3] = fmaf(v0, p4.w, acc[0][3]);
            acc[1][0] = fmaf(v1, p4.x, acc[1][0]);
            acc[1][1] = fmaf(v1, p4.y, acc[1][1]);
            acc[1][2] = fmaf(v1, p4.z, acc[1][2]);
            acc[1][3] = fmaf(v1, p4.w, acc[1][3]);
        }
    }

    // ---- fused epilogue: final conv + BN + SiLU + residual ----
    __syncthreads();
    float* Ys  = pool;           // [32][68] y_last tile
    float* W4s = pool + 2304;    // [256][32]
    float* s4s = pool + 10496;   // [256]
    float* b4s = pool + 10752;   // [256]

#pragma unroll
    for (int i = 0; i < 2; i++)
#pragma unroll
        for (int j = 0; j < 4; j++)
            Ys[(ty * 2 + i) * 68 + tx * 4 + j] = acc[i][j];
    for (int i = tid; i < C_ * CI; i += 256) W4s[i] = w4[i];
    s4s[tid] = s4[tid];
    b4s[tid] = b4[tid];
    __syncthreads();

    int m = tid & 63;
    int cg = tid >> 6;  // 0..3 -> 64 output channels each
    float yv[CI];
#pragma unroll
    for (int ci = 0; ci < CI; ci++) yv[ci] = Ys[ci * 68 + m];

    const float* xb = x + b * C_ * N_ + m0 + m;
    float* ob = out + b * C_ * N_ + m0 + m;
#pragma unroll 4
    for (int co = cg * 64; co < (cg + 1) * 64; ++co) {
        float s = 0.f;
#pragma unroll
        for (int c4 = 0; c4 < CI; c4 += 4) {
            float4 wv = *(const float4*)&W4s[co * CI + c4];
            s = fmaf(wv.x, yv[c4 + 0], s);
            s = fmaf(wv.y, yv[c4 + 1], s);
            s = fmaf(wv.z, yv[c4 + 2], s);
            s = fmaf(wv.w, yv[c4 + 3], s);
        }
        float yy = fmaf(s, s4s[co], b4s[co]);
        float sg = 1.f / (1.f + fexp2(-yy * L2E));
        ob[co * N_] = fmaf(yy, sg, __ldg(xb + co * N_));
    }
}

// ---------------------------------------------------------------------------
extern "C" void kernel_launch(void* const* d_in, const int* in_sizes, int n_in,
                              void* d_out, int out_size) {
    (void)in_sizes; (void)n_in; (void)out_size;
    const float* x  = (const float*)d_in[0];
    const float* w1 = (const float*)d_in[1];
    const float* s1 = (const float*)d_in[2];
    const float* b1 = (const float*)d_in[3];
    const float* w2 = (const float*)d_in[4];
    const float* s2 = (const float*)d_in[5];
    const float* b2 = (const float*)d_in[6];
    const float* w3 = (const float*)d_in[7];
    const float* s3 = (const float*)d_in[8];
    const float* b3 = (const float*)d_in[9];
    const float* w4 = (const float*)d_in[10];
    const float* s4 = (const float*)d_in[11];
    const float* b4 = (const float*)d_in[12];
    float* out = (float*)d_out;

    k0_transpose<<<3, 256>>>(w1, w2, w3);
    k1_conv<<<dim3(B_ * N_ / 128, 3), 128>>>(x, s1, b1, s2, b2, s3, b3);
    k2_stats<<<dim3(N_ / 64, B_), 256>>>();
    k3_attn<<<dim3(N_ / 64, B_), 256>>>(w4, s4, b4, x, out);
}